// round 1
// baseline (speedup 1.0000x reference)
#include <cuda_runtime.h>

#define BB   16
#define NN   4096
#define CC   64
#define KNNK 32
#define TILE 2048
#define QB   128

// Scratch (static device globals — allowed; no runtime allocation).
__device__ int   g_idx[BB * NN * KNNK];      // 8 MB
__device__ float g_mx[BB * NN * CC];         // 16 MB
__device__ float g_mn[BB * NN * CC];         // 16 MB
__device__ float g_part[BB * NN / 8];        // 8192 block partials
__device__ float g_inv;

// ---------------------------------------------------------------------------
// Kernel 1: exact 32-NN per point. Thread-per-query, shared-tiled candidates,
// local-memory max-heap of packed (monotone dist bits, idx).
// ---------------------------------------------------------------------------
__global__ void __launch_bounds__(QB) knn_kernel(const float* __restrict__ xyz) {
    __shared__ float4 s[TILE];                       // 32 KB

    const int b = blockIdx.x >> 5;                   // 32 blocks per batch
    const int i = ((blockIdx.x & 31) << 7) + threadIdx.x;
    const float* xb = xyz + (size_t)b * (3 * NN);

    const float xi = xb[i], yi = xb[NN + i], zi = xb[2 * NN + i];
    const float ax = -2.f * xi, ay = -2.f * yi, az = -2.f * zi;

    unsigned long long heap[KNNK];
#pragma unroll
    for (int t = 0; t < KNNK; t++) heap[t] = 0xFF800000FFFFFFFFULL;  // +inf key
    float worst = __int_as_float(0x7F800000);        // +inf

    for (int t0 = 0; t0 < NN; t0 += TILE) {
        __syncthreads();
        for (int t = threadIdx.x; t < TILE; t += QB) {
            float X = xb[t0 + t], Y = xb[NN + t0 + t], Z = xb[2 * NN + t0 + t];
            s[t] = make_float4(X, Y, Z, fmaf(X, X, fmaf(Y, Y, Z * Z)));
        }
        __syncthreads();

#pragma unroll 8
        for (int jj = 0; jj < TILE; ++jj) {
            float4 q = s[jj];
            // d_rel = ||xj||^2 - 2 xi.xj  (ranking-equivalent to reference pd)
            float d = fmaf(ax, q.x, fmaf(ay, q.y, fmaf(az, q.z, q.w)));
            if (d <= worst) {                        // rare path (~190/query)
                unsigned u = __float_as_uint(d);
                u ^= ((unsigned)((int)u >> 31)) | 0x80000000u;  // monotone map
                unsigned long long p =
                    ((unsigned long long)u << 32) | (unsigned)(t0 + jj);
                if (p < heap[0]) {
                    unsigned long long v = p;
                    int pos = 0;
                    while (true) {                   // sift-down, <=5 levels
                        int c = 2 * pos + 1;
                        if (c >= KNNK) break;
                        unsigned long long cv = heap[c];
                        if (c + 1 < KNNK) {
                            unsigned long long cv2 = heap[c + 1];
                            if (cv2 > cv) { cv = cv2; ++c; }
                        }
                        if (cv <= v) break;
                        heap[pos] = cv; pos = c;
                    }
                    heap[pos] = v;
                    unsigned wu = (unsigned)(heap[0] >> 32);
                    wu ^= (wu & 0x80000000u) ? 0x80000000u : 0xFFFFFFFFu;
                    worst = __uint_as_float(wu);
                }
            }
        }
    }

    const int base = (b * NN + i) * KNNK;
#pragma unroll
    for (int t = 0; t < KNNK; t++)
        g_idx[base + t] = (int)(heap[t] & 0xFFFFFFFFULL);
}

// ---------------------------------------------------------------------------
// Kernel 2: warp per (b,i). Lane = channel pair. Coalesced 256B row gathers.
// Produces per-channel max/min of offsets + block partial of sum(offset^2).
// ---------------------------------------------------------------------------
__global__ void __launch_bounds__(256) gather_kernel(const float* __restrict__ feats) {
    const int gw   = (blockIdx.x << 3) + (threadIdx.x >> 5);   // b*NN + i
    const int lane = threadIdx.x & 31;
    const int b = gw >> 12;
    const int i = gw & (NN - 1);
    const float* fb = feats + ((size_t)b << 18);               // b*NN*CC

    const float2 ctr = *(const float2*)(fb + i * CC + lane * 2);
    const int myid = g_idx[gw * KNNK + lane];

    float mx0 = __int_as_float(0xFF800000), mx1 = mx0;
    float mn0 = __int_as_float(0x7F800000), mn1 = mn0;
    float ss = 0.f;

#pragma unroll
    for (int k = 0; k < KNNK; k++) {
        int j = __shfl_sync(0xFFFFFFFFu, myid, k);
        float2 f = *(const float2*)(fb + j * CC + lane * 2);
        float o0 = f.x - ctr.x, o1 = f.y - ctr.y;
        mx0 = fmaxf(mx0, o0); mn0 = fminf(mn0, o0);
        mx1 = fmaxf(mx1, o1); mn1 = fminf(mn1, o1);
        ss = fmaf(o0, o0, ss);
        ss = fmaf(o1, o1, ss);
    }

    const int ob = gw * CC + lane * 2;
    *(float2*)(g_mx + ob) = make_float2(mx0, mx1);
    *(float2*)(g_mn + ob) = make_float2(mn0, mn1);

#pragma unroll
    for (int off = 16; off; off >>= 1)
        ss += __shfl_xor_sync(0xFFFFFFFFu, ss, off);

    __shared__ float bs[8];
    if (lane == 0) bs[threadIdx.x >> 5] = ss;
    __syncthreads();
    if (threadIdx.x == 0) {
        g_part[blockIdx.x] = bs[0] + bs[1] + bs[2] + bs[3] +
                             bs[4] + bs[5] + bs[6] + bs[7];
    }
}

// ---------------------------------------------------------------------------
// Kernel 3: reduce partials -> g_inv = 1/(sigma + eps)
// ---------------------------------------------------------------------------
__global__ void reduce_kernel() {
    __shared__ float sm[256];
    float s = 0.f;
    for (int t = threadIdx.x; t < BB * NN / 8; t += 256) s += g_part[t];
    sm[threadIdx.x] = s;
    __syncthreads();
#pragma unroll
    for (int o = 128; o; o >>= 1) {
        if (threadIdx.x < o) sm[threadIdx.x] += sm[threadIdx.x + o];
        __syncthreads();
    }
    if (threadIdx.x == 0) {
        float sigma = sm[0] / (float)((long long)BB * NN * KNNK * CC);
        g_inv = 1.f / (sigma + 1e-5f);
    }
}

// ---------------------------------------------------------------------------
// Kernel 4: pooled = select(alpha>=0, max, min) * inv * alpha + beta
// (max over k commutes with the positive/negative scale)
// ---------------------------------------------------------------------------
__global__ void __launch_bounds__(256) final_kernel(const float* __restrict__ alpha,
                                                    const float* __restrict__ beta,
                                                    float* __restrict__ out) {
    const int idx = blockIdx.x * 256 + threadIdx.x;   // float2 index, 2M total
    const float inv = g_inv;
    const int c2 = idx & (CC / 2 - 1);
    const float a0 = alpha[c2 * 2], a1 = alpha[c2 * 2 + 1];
    const float b0 = beta[c2 * 2],  b1 = beta[c2 * 2 + 1];
    const float2 mx = ((const float2*)g_mx)[idx];
    const float2 mn = ((const float2*)g_mn)[idx];
    float v0 = (a0 >= 0.f) ? mx.x : mn.x;
    float v1 = (a1 >= 0.f) ? mx.y : mn.y;
    float2 r;
    r.x = fmaf(v0 * inv, a0, b0);
    r.y = fmaf(v1 * inv, a1, b1);
    ((float2*)out)[idx] = r;
}

extern "C" void kernel_launch(void* const* d_in, const int* in_sizes, int n_in,
                              void* d_out, int out_size) {
    const float* xyz   = (const float*)d_in[0];
    const float* feats = (const float*)d_in[1];
    const float* alpha = (const float*)d_in[2];
    const float* beta  = (const float*)d_in[3];
    float* out = (float*)d_out;
    (void)in_sizes; (void)n_in; (void)out_size;

    knn_kernel<<<BB * NN / QB, QB>>>(xyz);
    gather_kernel<<<BB * NN / 8, 256>>>(feats);
    reduce_kernel<<<1, 256>>>();
    final_kernel<<<BB * NN * CC / 512, 256>>>(alpha, beta, out);
}

// round 2
// speedup vs baseline: 6.4221x; 6.4221x over previous
#include <cuda_runtime.h>

#define BB   16
#define NN   4096
#define CC   64
#define KNNK 32
#define TILE 2048
#define QB   128

#define F_INF __int_as_float(0x7f800000)

// Scratch (static device globals — allowed; no runtime allocation).
__device__ int   g_idx[BB * NN * KNNK];      // 8 MB
__device__ float g_mx[BB * NN * CC];         // 16 MB
__device__ float g_mn[BB * NN * CC];         // 16 MB
__device__ float g_part[BB * NN / 8];        // 8192 block partials
__device__ float g_inv;

// Branchless insert of c into ascending sorted 32-reg array (drops old max).
__device__ __forceinline__ void insert32(float (&sv)[KNNK], float c) {
#pragma unroll
    for (int u = 0; u < KNNK; u++) {
        float lo = fminf(sv[u], c);
        c = fmaxf(sv[u], c);
        sv[u] = lo;
    }
}

// ---------------------------------------------------------------------------
// Kernel 1: exact 32-NN per point, two-phase register-only selection.
// Phase 1: exact 32nd-smallest distance per query (values only, FMNMX chains).
// Phase 2: rescan, emit index set (asc. index order, jax-compatible ties).
// ---------------------------------------------------------------------------
__global__ void __launch_bounds__(QB) knn_kernel(const float* __restrict__ xyz) {
    __shared__ float4 tile[TILE];                    // 32 KB

    const int b = blockIdx.x >> 5;                   // 32 blocks per batch
    const int i = ((blockIdx.x & 31) << 7) + threadIdx.x;
    const float* xb = xyz + (size_t)b * (3 * NN);

    const float xi = xb[i], yi = xb[NN + i], zi = xb[2 * NN + i];
    const float ax = -2.f * xi, ay = -2.f * yi, az = -2.f * zi;

    float sv[KNNK];
#pragma unroll
    for (int u = 0; u < KNNK; u++) sv[u] = F_INF;
    float worst = F_INF;
    float b0 = F_INF, b1 = F_INF, b2 = F_INF, b3 = F_INF;
    int cnt = 0;

    // ---------------- Phase 1: exact 32 smallest distance VALUES ----------
    for (int t0 = 0; t0 < NN; t0 += TILE) {
        __syncthreads();
        for (int t = threadIdx.x; t < TILE; t += QB) {
            float X = xb[t0 + t], Y = xb[NN + t0 + t], Z = xb[2 * NN + t0 + t];
            tile[t] = make_float4(X, Y, Z, fmaf(X, X, fmaf(Y, Y, Z * Z)));
        }
        __syncthreads();

#pragma unroll 4
        for (int jj = 0; jj < TILE; ++jj) {
            float4 q = tile[jj];
            // d_rel = ||xj||^2 - 2 xi.xj  (ranking-equivalent to reference pd)
            float d = fmaf(ax, q.x, fmaf(ay, q.y, fmaf(az, q.z, q.w)));
            bool p = d < worst;                      // strict: exact for values
            if (__any_sync(0xFFFFFFFFu, p)) {
                if (p) { b3 = b2; b2 = b1; b1 = b0; b0 = d; cnt++; }
                if (__any_sync(0xFFFFFFFFu, cnt >= 4)) {
                    insert32(sv, b0); insert32(sv, b1);
                    insert32(sv, b2); insert32(sv, b3);
                    b0 = b1 = b2 = b3 = F_INF; cnt = 0;
                    worst = sv[KNNK - 1];
                }
            }
        }
    }
    // final flush (sentinels are harmless)
    insert32(sv, b0); insert32(sv, b1); insert32(sv, b2); insert32(sv, b3);

    const float w = sv[KNNK - 1];                    // exact 32nd smallest
    int ties = 1;                                    // allowed emissions == w
#pragma unroll
    for (int u = 0; u < KNNK - 1; u++) ties += (sv[u] == w);

    // ---------------- Phase 2: recover the index set ----------------------
    const int base = (b * NN + i) * KNNK;
    int cnt2 = 0;
    for (int t0 = 0; t0 < NN; t0 += TILE) {
        __syncthreads();
        for (int t = threadIdx.x; t < TILE; t += QB) {
            float X = xb[t0 + t], Y = xb[NN + t0 + t], Z = xb[2 * NN + t0 + t];
            tile[t] = make_float4(X, Y, Z, fmaf(X, X, fmaf(Y, Y, Z * Z)));
        }
        __syncthreads();

#pragma unroll 4
        for (int jj = 0; jj < TILE; ++jj) {
            float4 q = tile[jj];
            float d = fmaf(ax, q.x, fmaf(ay, q.y, fmaf(az, q.z, q.w)));
            bool lt = d < w;
            bool eq = (d == w);
            if (__any_sync(0xFFFFFFFFu, lt | eq)) {
                if (lt | (eq & (ties > 0))) {
                    g_idx[base + cnt2] = t0 + jj;
                    cnt2++;
                    ties -= eq ? 1 : 0;
                }
            }
        }
    }
}

// ---------------------------------------------------------------------------
// Kernel 2: warp per (b,i). Lane = channel pair. Coalesced 256B row gathers.
// Produces per-channel max/min of offsets + block partial of sum(offset^2).
// ---------------------------------------------------------------------------
__global__ void __launch_bounds__(256) gather_kernel(const float* __restrict__ feats) {
    const int gw   = (blockIdx.x << 3) + (threadIdx.x >> 5);   // b*NN + i
    const int lane = threadIdx.x & 31;
    const int b = gw >> 12;
    const int i = gw & (NN - 1);
    const float* fb = feats + ((size_t)b << 18);               // b*NN*CC

    const float2 ctr = *(const float2*)(fb + i * CC + lane * 2);
    const int myid = g_idx[gw * KNNK + lane];

    float mx0 = __int_as_float(0xFF800000), mx1 = mx0;
    float mn0 = F_INF, mn1 = F_INF;
    float ss = 0.f;

#pragma unroll
    for (int k = 0; k < KNNK; k++) {
        int j = __shfl_sync(0xFFFFFFFFu, myid, k);
        float2 f = *(const float2*)(fb + j * CC + lane * 2);
        float o0 = f.x - ctr.x, o1 = f.y - ctr.y;
        mx0 = fmaxf(mx0, o0); mn0 = fminf(mn0, o0);
        mx1 = fmaxf(mx1, o1); mn1 = fminf(mn1, o1);
        ss = fmaf(o0, o0, ss);
        ss = fmaf(o1, o1, ss);
    }

    const int ob = gw * CC + lane * 2;
    *(float2*)(g_mx + ob) = make_float2(mx0, mx1);
    *(float2*)(g_mn + ob) = make_float2(mn0, mn1);

#pragma unroll
    for (int off = 16; off; off >>= 1)
        ss += __shfl_xor_sync(0xFFFFFFFFu, ss, off);

    __shared__ float bs[8];
    if (lane == 0) bs[threadIdx.x >> 5] = ss;
    __syncthreads();
    if (threadIdx.x == 0) {
        g_part[blockIdx.x] = bs[0] + bs[1] + bs[2] + bs[3] +
                             bs[4] + bs[5] + bs[6] + bs[7];
    }
}

// ---------------------------------------------------------------------------
// Kernel 3: reduce partials -> g_inv = 1/(sigma + eps)
// ---------------------------------------------------------------------------
__global__ void reduce_kernel() {
    __shared__ float sm[256];
    float s = 0.f;
    for (int t = threadIdx.x; t < BB * NN / 8; t += 256) s += g_part[t];
    sm[threadIdx.x] = s;
    __syncthreads();
#pragma unroll
    for (int o = 128; o; o >>= 1) {
        if (threadIdx.x < o) sm[threadIdx.x] += sm[threadIdx.x + o];
        __syncthreads();
    }
    if (threadIdx.x == 0) {
        float sigma = sm[0] / (float)((long long)BB * NN * KNNK * CC);
        g_inv = 1.f / (sigma + 1e-5f);
    }
}

// ---------------------------------------------------------------------------
// Kernel 4: pooled = select(alpha>=0, max, min) * inv * alpha + beta
// (max over k commutes with the positive/negative scale)
// ---------------------------------------------------------------------------
__global__ void __launch_bounds__(256) final_kernel(const float* __restrict__ alpha,
                                                    const float* __restrict__ beta,
                                                    float* __restrict__ out) {
    const int idx = blockIdx.x * 256 + threadIdx.x;   // float2 index, 2M total
    const float inv = g_inv;
    const int c2 = idx & (CC / 2 - 1);
    const float a0 = alpha[c2 * 2], a1 = alpha[c2 * 2 + 1];
    const float b0 = beta[c2 * 2],  b1 = beta[c2 * 2 + 1];
    const float2 mx = ((const float2*)g_mx)[idx];
    const float2 mn = ((const float2*)g_mn)[idx];
    float v0 = (a0 >= 0.f) ? mx.x : mn.x;
    float v1 = (a1 >= 0.f) ? mx.y : mn.y;
    float2 r;
    r.x = fmaf(v0 * inv, a0, b0);
    r.y = fmaf(v1 * inv, a1, b1);
    ((float2*)out)[idx] = r;
}

extern "C" void kernel_launch(void* const* d_in, const int* in_sizes, int n_in,
                              void* d_out, int out_size) {
    const float* xyz   = (const float*)d_in[0];
    const float* feats = (const float*)d_in[1];
    const float* alpha = (const float*)d_in[2];
    const float* beta  = (const float*)d_in[3];
    float* out = (float*)d_out;
    (void)in_sizes; (void)n_in; (void)out_size;

    knn_kernel<<<BB * NN / QB, QB>>>(xyz);
    gather_kernel<<<BB * NN / 8, 256>>>(feats);
    reduce_kernel<<<1, 256>>>();
    final_kernel<<<BB * NN * CC / 512, 256>>>(alpha, beta, out);
}